// round 16
// baseline (speedup 1.0000x reference)
#include <cuda_runtime.h>
#include <cuda_fp16.h>

#define NN 86016
#define NE 4194304
#define H 32
#define NG 1024
#define NPG 84
#define CAP 128
#define SCB (NE / 1024)
#define BIG_NEG -1e30f

struct __align__(8) Ent { int src; __half2 ea; };

// ---------------- device scratch ----------------
__device__ int    d_cur[NN];
__device__ Ent    d_ent[NN * CAP];
__device__ __half d_h16A[NN * H];
__device__ __half d_h16B[NN * H];
__device__ float  d_pool1[NG];
__device__ __half d_asA[NN], d_asB[NN];
__device__ float  d_adA[NN], d_adB[NN];
__device__ float2 d_ce[4];
__device__ float  d_c0[2];

// ---------------- init: cur=1, self-loop slot, pool=0, folded constants ----------------
__global__ void k_initc(const float* __restrict__ W0, const float* __restrict__ a_s,
                        const float* __restrict__ a_d, const float* __restrict__ We,
                        const float* __restrict__ a_e) {
    int i = blockIdx.x * blockDim.x + threadIdx.x;
    if (i < NN) {
        d_cur[i] = 1;
        ((int2*)d_ent)[i * CAP] = make_int2(i, 0);
    }
    if (i < NG) d_pool1[i] = 0.f;
    if (blockIdx.x == 0 && threadIdx.x < 160) {
        int w = threadIdx.x >> 5, lane = threadIdx.x & 31;
        if (w < 4) {
            float ae = a_e[w * 32 + lane];
            float p0 = We[w * 64 + lane] * ae;
            float p1 = We[w * 64 + 32 + lane] * ae;
            #pragma unroll
            for (int o = 16; o; o >>= 1) {
                p0 += __shfl_xor_sync(~0u, p0, o);
                p1 += __shfl_xor_sync(~0u, p1, o);
            }
            if (lane == 0) d_ce[w] = make_float2(p0, p1);
        } else {
            float w0 = W0[lane];
            float ps = w0 * a_s[lane];
            float pd = w0 * a_d[lane];
            #pragma unroll
            for (int o = 16; o; o >>= 1) {
                ps += __shfl_xor_sync(~0u, ps, o);
                pd += __shfl_xor_sync(~0u, pd, o);
            }
            if (lane == 0) { d_c0[0] = ps; d_c0[1] = pd; }
        }
    }
}

// ---------------- scatter into fixed-capacity rows + layer0 transform ----------------
__global__ void k_scatl0(const int* __restrict__ ei, const float2* __restrict__ ea,
                         const float* __restrict__ x, const float* __restrict__ W0) {
    if (blockIdx.x < SCB) {
        int e = (blockIdx.x * 256 + threadIdx.x) * 4;
        int4 s = *(const int4*)(ei + e);
        int4 d = *(const int4*)(ei + NE + e);
        float4 a01 = *(const float4*)(ea + e);
        float4 a23 = *(const float4*)(ea + e + 2);
        int2* ent = (int2*)d_ent;
        __half2 h0 = __floats2half2_rn(a01.x, a01.y);
        __half2 h1 = __floats2half2_rn(a01.z, a01.w);
        __half2 h2 = __floats2half2_rn(a23.x, a23.y);
        __half2 h3 = __floats2half2_rn(a23.z, a23.w);
        int p;
        p = atomicAdd(&d_cur[d.x], 1); ent[d.x * CAP + p] = make_int2(s.x, *(int*)&h0);
        p = atomicAdd(&d_cur[d.y], 1); ent[d.y * CAP + p] = make_int2(s.y, *(int*)&h1);
        p = atomicAdd(&d_cur[d.z], 1); ent[d.z * CAP + p] = make_int2(s.z, *(int*)&h2);
        p = atomicAdd(&d_cur[d.w], 1); ent[d.w * CAP + p] = make_int2(s.w, *(int*)&h3);
    } else {
        int bid = blockIdx.x - SCB;
        int lane = threadIdx.x & 31;
        int n = bid * 8 + (threadIdx.x >> 5);
        float v = x[n];
        d_h16B[n * H + lane] = __float2half(v * W0[lane]);
        if (lane == 0) { d_asA[n] = __float2half(v * d_c0[0]); d_adA[n] = v * d_c0[1]; }
    }
}

// ---------------- GAT agg (+ fused next-layer transform / final pool) ----------------
// FUSED=1: relu + Wnext + write next h/asrc/adst.
// FUSED=0: last layer; asn = lin_w; warp-dot + atomicAdd into d_pool1[graph].
template<int FUSED>
__global__ void k_agg(const __half* __restrict__ hlin,
                      const float* __restrict__ bias, int layer,
                      const float* __restrict__ Wn, const float* __restrict__ asn,
                      const float* __restrict__ adn,
                      const __half* __restrict__ asrc_in, const float* __restrict__ adst_in,
                      __half* __restrict__ hout16, float* __restrict__ pool1,
                      __half* __restrict__ asrc_out, float* __restrict__ adst_out) {
    __shared__ float Ws[H * H];
    __shared__ float As[H], Ad[H];
    __shared__ uint2 smp[8][128];
    int t = threadIdx.x;
    if (FUSED) {
        for (int i = t; i < H * H; i += 256) Ws[i] = Wn[i];
        if (t < H) { As[t] = asn[t]; Ad[t] = adn[t]; }
        __syncthreads();
    } else {
        if (t < H) As[t] = asn[t];    // lin_w
        __syncthreads();
    }

    int lane = t & 31;
    int wid = t >> 5;
    int n = blockIdx.x * 8 + wid;
    float2 ce = d_ce[layer];
    int rs = n * CAP;
    int len = d_cur[n];
    int re = rs + len;
    float adv = adst_in[n];
    int nch = (len + 31) >> 5;
    bool fast = (nch <= 4);           // always true (len <= CAP)
    const int2* ent2 = (const int2*)d_ent;
    const uint2* h2x2 = (const uint2*)hlin;
    float degc = (float)((len > 2) ? (len - 1) : 1);

    float o;
    if (fast) {
        // ---- phase 1: logits (self deferred) + ea sums ----
        int sv[4]; float lv[4];
        #pragma unroll
        for (int c = 0; c < 4; c++) { sv[c] = 0; lv[c] = BIG_NEG; }
        float sx = 0.f, sy = 0.f;
        #pragma unroll
        for (int c = 0; c < 4; c++) {
            if (c < nch) {
                int e = rs + c * 32 + lane;
                if (e < re) {
                    int2 ev = ent2[e];
                    __half2 eah = *reinterpret_cast<__half2*>(&ev.y);
                    float2 eaf = __half22float2(eah);
                    sv[c] = ev.x;
                    if (e != rs) {
                        sx += eaf.x; sy += eaf.y;
                        float l = __half2float(asrc_in[ev.x]) + adv + eaf.x * ce.x + eaf.y * ce.y;
                        lv[c] = (l >= 0.f) ? l : 0.2f * l;
                    }
                }
            }
        }
        #pragma unroll
        for (int off = 16; off; off >>= 1) {
            sx += __shfl_xor_sync(~0u, sx, off);
            sy += __shfl_xor_sync(~0u, sy, off);
        }
        if (lane == 0) {
            float mex = sx / degc, mey = sy / degc;
            float l = __half2float(asrc_in[n]) + adv + mex * ce.x + mey * ce.y;
            lv[0] = (l >= 0.f) ? l : 0.2f * l;
        }
        float m = fmaxf(fmaxf(lv[0], lv[1]), fmaxf(lv[2], lv[3]));
        #pragma unroll
        for (int off = 16; off; off >>= 1)
            m = fmaxf(m, __shfl_xor_sync(~0u, m, off));

        // ---- one exp per edge, pairs to smem ----
        float ssum = 0.f;
        #pragma unroll
        for (int c = 0; c < 4; c++) {
            if (c < nch) {
                float w = __expf(lv[c] - m);
                ssum += w;
                smp[wid][c * 32 + lane] = make_uint2(__float_as_uint(w), (unsigned)sv[c]);
            }
        }
        __syncwarp();
        #pragma unroll
        for (int off = 16; off; off >>= 1)
            ssum += __shfl_xor_sync(~0u, ssum, off);
        float inv_s = 1.f / ssum;

        // ---- phase 2: 8 lanes/row, LDG.64, smem pair broadcast, no guards ----
        int g  = lane >> 3;
        int fo = lane & 7;
        float4 acc = make_float4(0.f, 0.f, 0.f, 0.f);
        #pragma unroll
        for (int c = 0; c < 4; c++) {
            if (c < nch) {
                const uint2* pp = &smp[wid][c * 32];
                #pragma unroll
                for (int p = 0; p < 32; p += 4) {
                    uint2 pr = pp[p + g];
                    float w = __uint_as_float(pr.x);
                    uint2 rv = h2x2[(int)pr.y * 8 + fo];
                    float2 fa = __half22float2(*reinterpret_cast<__half2*>(&rv.x));
                    float2 fb = __half22float2(*reinterpret_cast<__half2*>(&rv.y));
                    acc.x = fmaf(w, fa.x, acc.x);
                    acc.y = fmaf(w, fa.y, acc.y);
                    acc.z = fmaf(w, fb.x, acc.z);
                    acc.w = fmaf(w, fb.y, acc.w);
                }
            }
        }
        #pragma unroll
        for (int off = 8; off <= 16; off <<= 1) {
            acc.x += __shfl_xor_sync(~0u, acc.x, off);
            acc.y += __shfl_xor_sync(~0u, acc.y, off);
            acc.z += __shfl_xor_sync(~0u, acc.z, off);
            acc.w += __shfl_xor_sync(~0u, acc.w, off);
        }
        int srcl = lane >> 2;
        float c0 = __shfl_sync(~0u, acc.x, srcl);
        float c1 = __shfl_sync(~0u, acc.y, srcl);
        float c2 = __shfl_sync(~0u, acc.z, srcl);
        float c3 = __shfl_sync(~0u, acc.w, srcl);
        int k = lane & 3;
        float sel = (k == 0) ? c0 : (k == 1) ? c1 : (k == 2) ? c2 : c3;
        o = sel * inv_s + bias[lane];
    } else {
        // ---- streaming fallback (unreachable with CAP=128; safety) ----
        float sx = 0.f, sy = 0.f;
        for (int e = rs + 1 + lane; e < re; e += 32) {
            int2 ev = ent2[e];
            float2 a = __half22float2(*reinterpret_cast<__half2*>(&ev.y));
            sx += a.x; sy += a.y;
        }
        #pragma unroll
        for (int off = 16; off; off >>= 1) {
            sx += __shfl_xor_sync(~0u, sx, off);
            sy += __shfl_xor_sync(~0u, sy, off);
        }
        float mex = sx / degc, mey = sy / degc;
        float m = BIG_NEG, s = 0.f;
        for (int b = rs; b < re; b += 32) {
            int e = b + lane;
            if (e < re) {
                int2 ev = ent2[e];
                float2 eaf = __half22float2(*reinterpret_cast<__half2*>(&ev.y));
                if (e == rs) { eaf.x = mex; eaf.y = mey; }
                float l = __half2float(asrc_in[ev.x]) + adv + eaf.x * ce.x + eaf.y * ce.y;
                l = (l >= 0.f) ? l : 0.2f * l;
                if (l > m) { s = s * __expf(m - l) + 1.f; m = l; }
                else       { s += __expf(l - m); }
            }
        }
        #pragma unroll
        for (int off = 16; off; off >>= 1) {
            float mo = __shfl_xor_sync(~0u, m, off);
            float so = __shfl_xor_sync(~0u, s, off);
            float mn = fmaxf(m, mo);
            s = s * __expf(m - mn) + so * __expf(mo - mn);
            m = mn;
        }
        float inv_s = 1.f / s;
        float acc = 0.f;
        for (int b = rs; b < re; b += 32) {
            int e = b + lane;
            float w = 0.f; int srcn = 0;
            if (e < re) {
                int2 ev = ent2[e];
                float2 eaf = __half22float2(*reinterpret_cast<__half2*>(&ev.y));
                if (e == rs) { eaf.x = mex; eaf.y = mey; }
                float l = __half2float(asrc_in[ev.x]) + adv + eaf.x * ce.x + eaf.y * ce.y;
                l = (l >= 0.f) ? l : 0.2f * l;
                w = __expf(l - m) * inv_s;
                srcn = ev.x;
            }
            int cw = min(32, re - b);
            #pragma unroll 4
            for (int j = 0; j < cw; j++) {
                int   sj = __shfl_sync(~0u, srcn, j);
                float wj = __shfl_sync(~0u, w, j);
                acc = fmaf(wj, __half2float(hlin[sj * H + lane]), acc);
            }
        }
        o = acc + bias[lane];
    }

    if (FUSED) {
        o = fmaxf(o, 0.f);
        float hn = 0.f;
        #pragma unroll
        for (int k2 = 0; k2 < H; k2++)
            hn = fmaf(__shfl_sync(~0u, o, k2), Ws[k2 * H + lane], hn);
        hout16[n * H + lane] = __float2half(hn);
        float ps = hn * As[lane], pd = hn * Ad[lane];
        #pragma unroll
        for (int off = 16; off; off >>= 1) {
            ps += __shfl_xor_sync(~0u, ps, off);
            pd += __shfl_xor_sync(~0u, pd, off);
        }
        if (lane == 0) { asrc_out[n] = __float2half(ps); adst_out[n] = pd; }
    } else {
        // final layer: dot with lin_w, accumulate per-graph
        float ps = o * As[lane];
        #pragma unroll
        for (int off = 16; off; off >>= 1)
            ps += __shfl_xor_sync(~0u, ps, off);
        if (lane == 0) atomicAdd(&pool1[n / NPG], ps);
    }
}

// ---------------- finalize: relu(pool + lb) ----------------
__global__ void k_fin(const float* __restrict__ lb, float* __restrict__ out) {
    int g = blockIdx.x * 256 + threadIdx.x;
    if (g < NG) out[g] = fmaxf(d_pool1[g] + lb[0], 0.f);
}

// ---------------- launch ----------------
extern "C" void kernel_launch(void* const* d_in, const int* in_sizes, int n_in,
                              void* d_out, int out_size) {
    const float*  x    = (const float*)d_in[0];
    const int*    ei   = (const int*)d_in[1];
    const float2* ea   = (const float2*)d_in[2];
    const float*  W0   = (const float*)d_in[3];
    const float*  Ws   = (const float*)d_in[4];
    const float*  as_  = (const float*)d_in[5];
    const float*  ad_  = (const float*)d_in[6];
    const float*  We   = (const float*)d_in[7];
    const float*  ae_  = (const float*)d_in[8];
    const float*  bias = (const float*)d_in[9];
    const float*  lw   = (const float*)d_in[10];
    const float*  lb   = (const float*)d_in[11];
    float* out = (float*)d_out;

    __half *hA, *hB, *asA, *asB; float *p1, *adA, *adB;
    cudaGetSymbolAddress((void**)&hA, d_h16A);
    cudaGetSymbolAddress((void**)&hB, d_h16B);
    cudaGetSymbolAddress((void**)&p1, d_pool1);
    cudaGetSymbolAddress((void**)&asA, d_asA);
    cudaGetSymbolAddress((void**)&asB, d_asB);
    cudaGetSymbolAddress((void**)&adA, d_adA);
    cudaGetSymbolAddress((void**)&adB, d_adB);

    k_initc<<<(NN + 255) / 256, 256>>>(W0, as_, ad_, We, ae_);
    k_scatl0<<<SCB + NN / 8, 256>>>(ei, ea, x, W0);

    k_agg<1><<<NN / 8, 256>>>(hB, bias + 0 * H, 0, Ws + 0 * H * H, as_ + 1 * H, ad_ + 1 * H,
                              asA, adA, hA, nullptr, asB, adB);
    k_agg<1><<<NN / 8, 256>>>(hA, bias + 1 * H, 1, Ws + 1 * H * H, as_ + 2 * H, ad_ + 2 * H,
                              asB, adB, hB, nullptr, asA, adA);
    k_agg<1><<<NN / 8, 256>>>(hB, bias + 2 * H, 2, Ws + 2 * H * H, as_ + 3 * H, ad_ + 3 * H,
                              asA, adA, hA, nullptr, asB, adB);
    k_agg<0><<<NN / 8, 256>>>(hA, bias + 3 * H, 3, nullptr, lw, nullptr,
                              asB, adB, nullptr, p1, nullptr, nullptr);
    k_fin<<<4, 256>>>(lb, out);
}

// round 17
// speedup vs baseline: 1.0365x; 1.0365x over previous
#include <cuda_runtime.h>
#include <cuda_fp16.h>

#define NN 86016
#define NE 4194304
#define H 32
#define NG 1024
#define NPG 84
#define CAP 128
#define SCB (NE / 1024)
#define BIG_NEG -1e30f

struct __align__(8) Ent { int src; __half2 ea; };

// ---------------- device scratch ----------------
__device__ int    d_cur[NN];
__device__ Ent    d_ent[NN * CAP];
__device__ __half d_h16A[NN * H];
__device__ __half d_h16B[NN * H];
__device__ float  d_hfin[NN * H];
__device__ float2 d_mea[NN];          // per-node mean edge attr (layer-invariant)
__device__ __half d_asA[NN], d_asB[NN];
__device__ float  d_adA[NN], d_adB[NN];
__device__ float2 d_ce[4];
__device__ float  d_c0[2];

// ---------------- init: cur=1, self-loop slot, folded constants ----------------
__global__ void k_initc(const float* __restrict__ W0, const float* __restrict__ a_s,
                        const float* __restrict__ a_d, const float* __restrict__ We,
                        const float* __restrict__ a_e) {
    int i = blockIdx.x * blockDim.x + threadIdx.x;
    if (i < NN) {
        d_cur[i] = 1;
        ((int2*)d_ent)[i * CAP] = make_int2(i, 0);
    }
    if (blockIdx.x == 0 && threadIdx.x < 160) {
        int w = threadIdx.x >> 5, lane = threadIdx.x & 31;
        if (w < 4) {
            float ae = a_e[w * 32 + lane];
            float p0 = We[w * 64 + lane] * ae;
            float p1 = We[w * 64 + 32 + lane] * ae;
            #pragma unroll
            for (int o = 16; o; o >>= 1) {
                p0 += __shfl_xor_sync(~0u, p0, o);
                p1 += __shfl_xor_sync(~0u, p1, o);
            }
            if (lane == 0) d_ce[w] = make_float2(p0, p1);
        } else {
            float w0 = W0[lane];
            float ps = w0 * a_s[lane];
            float pd = w0 * a_d[lane];
            #pragma unroll
            for (int o = 16; o; o >>= 1) {
                ps += __shfl_xor_sync(~0u, ps, o);
                pd += __shfl_xor_sync(~0u, pd, o);
            }
            if (lane == 0) { d_c0[0] = ps; d_c0[1] = pd; }
        }
    }
}

// ---------------- scatter into fixed-capacity rows + layer0 transform ----------------
__global__ void k_scatl0(const int* __restrict__ ei, const float2* __restrict__ ea,
                         const float* __restrict__ x, const float* __restrict__ W0) {
    if (blockIdx.x < SCB) {
        int e = (blockIdx.x * 256 + threadIdx.x) * 4;
        int4 s = *(const int4*)(ei + e);
        int4 d = *(const int4*)(ei + NE + e);
        float4 a01 = *(const float4*)(ea + e);
        float4 a23 = *(const float4*)(ea + e + 2);
        int2* ent = (int2*)d_ent;
        __half2 h0 = __floats2half2_rn(a01.x, a01.y);
        __half2 h1 = __floats2half2_rn(a01.z, a01.w);
        __half2 h2 = __floats2half2_rn(a23.x, a23.y);
        __half2 h3 = __floats2half2_rn(a23.z, a23.w);
        int p;
        p = atomicAdd(&d_cur[d.x], 1); ent[d.x * CAP + p] = make_int2(s.x, *(int*)&h0);
        p = atomicAdd(&d_cur[d.y], 1); ent[d.y * CAP + p] = make_int2(s.y, *(int*)&h1);
        p = atomicAdd(&d_cur[d.z], 1); ent[d.z * CAP + p] = make_int2(s.z, *(int*)&h2);
        p = atomicAdd(&d_cur[d.w], 1); ent[d.w * CAP + p] = make_int2(s.w, *(int*)&h3);
    } else {
        int bid = blockIdx.x - SCB;
        int lane = threadIdx.x & 31;
        int n = bid * 8 + (threadIdx.x >> 5);
        float v = x[n];
        d_h16B[n * H + lane] = __float2half(v * W0[lane]);
        if (lane == 0) { d_asA[n] = __float2half(v * d_c0[0]); d_adA[n] = v * d_c0[1]; }
    }
}

// ---------------- GAT agg (+ fused next-layer transform) ----------------
// MEA=0 (layer 0): compute mean edge-attr from row, store to d_mea.
// MEA=1 (layers 1+): load d_mea, skip per-edge ea sums + reductions.
template<int FUSED, int MEA>
__global__ void k_agg(const __half* __restrict__ hlin,
                      const float* __restrict__ bias, int layer,
                      const float* __restrict__ Wn, const float* __restrict__ asn,
                      const float* __restrict__ adn,
                      const __half* __restrict__ asrc_in, const float* __restrict__ adst_in,
                      __half* __restrict__ hout16, float* __restrict__ houtf,
                      __half* __restrict__ asrc_out, float* __restrict__ adst_out) {
    __shared__ float Ws[H * H];
    __shared__ float As[H], Ad[H];
    __shared__ uint2 smp[8][128];
    int t = threadIdx.x;
    if (FUSED) {
        for (int i = t; i < H * H; i += 256) Ws[i] = Wn[i];
        if (t < H) { As[t] = asn[t]; Ad[t] = adn[t]; }
        __syncthreads();
    }

    int lane = t & 31;
    int wid = t >> 5;
    int n = blockIdx.x * 8 + wid;
    float2 ce = d_ce[layer];
    int rs = n * CAP;
    int len = d_cur[n];
    int re = rs + len;
    float adv = adst_in[n];
    int nch = (len + 31) >> 5;
    bool fast = (nch <= 4);           // always true (len <= CAP)
    const int2* ent2 = (const int2*)d_ent;
    const uint2* h2x2 = (const uint2*)hlin;
    float degc = (float)((len > 2) ? (len - 1) : 1);

    float o;
    if (fast) {
        // ---- phase 1: logits (self deferred); ea sums only when MEA==0 ----
        int sv[4]; float lv[4];
        #pragma unroll
        for (int c = 0; c < 4; c++) { sv[c] = 0; lv[c] = BIG_NEG; }
        float sx = 0.f, sy = 0.f;
        #pragma unroll
        for (int c = 0; c < 4; c++) {
            if (c < nch) {
                int e = rs + c * 32 + lane;
                if (e < re) {
                    int2 ev = ent2[e];
                    __half2 eah = *reinterpret_cast<__half2*>(&ev.y);
                    float2 eaf = __half22float2(eah);
                    sv[c] = ev.x;
                    if (e != rs) {
                        if (MEA == 0) { sx += eaf.x; sy += eaf.y; }
                        float l = __half2float(asrc_in[ev.x]) + adv + eaf.x * ce.x + eaf.y * ce.y;
                        lv[c] = (l >= 0.f) ? l : 0.2f * l;
                    }
                }
            }
        }
        float mex, mey;
        if (MEA == 0) {
            #pragma unroll
            for (int off = 16; off; off >>= 1) {
                sx += __shfl_xor_sync(~0u, sx, off);
                sy += __shfl_xor_sync(~0u, sy, off);
            }
            mex = sx / degc; mey = sy / degc;
            if (lane == 0) d_mea[n] = make_float2(mex, mey);
        } else {
            float2 mv = d_mea[n];
            mex = mv.x; mey = mv.y;
        }
        if (lane == 0) {
            float l = __half2float(asrc_in[n]) + adv + mex * ce.x + mey * ce.y;
            lv[0] = (l >= 0.f) ? l : 0.2f * l;
        }
        float m = fmaxf(fmaxf(lv[0], lv[1]), fmaxf(lv[2], lv[3]));
        #pragma unroll
        for (int off = 16; off; off >>= 1)
            m = fmaxf(m, __shfl_xor_sync(~0u, m, off));

        // ---- one exp per edge, pairs to smem ----
        float ssum = 0.f;
        #pragma unroll
        for (int c = 0; c < 4; c++) {
            if (c < nch) {
                float w = __expf(lv[c] - m);
                ssum += w;
                smp[wid][c * 32 + lane] = make_uint2(__float_as_uint(w), (unsigned)sv[c]);
            }
        }
        __syncwarp();
        #pragma unroll
        for (int off = 16; off; off >>= 1)
            ssum += __shfl_xor_sync(~0u, ssum, off);
        float inv_s = 1.f / ssum;

        // ---- phase 2: 8 lanes/row, LDG.64, smem pair broadcast, no guards ----
        int g  = lane >> 3;
        int fo = lane & 7;
        float4 acc = make_float4(0.f, 0.f, 0.f, 0.f);
        #pragma unroll
        for (int c = 0; c < 4; c++) {
            if (c < nch) {
                const uint2* pp = &smp[wid][c * 32];
                #pragma unroll
                for (int p = 0; p < 32; p += 4) {
                    uint2 pr = pp[p + g];
                    float w = __uint_as_float(pr.x);
                    uint2 rv = h2x2[(int)pr.y * 8 + fo];
                    float2 fa = __half22float2(*reinterpret_cast<__half2*>(&rv.x));
                    float2 fb = __half22float2(*reinterpret_cast<__half2*>(&rv.y));
                    acc.x = fmaf(w, fa.x, acc.x);
                    acc.y = fmaf(w, fa.y, acc.y);
                    acc.z = fmaf(w, fb.x, acc.z);
                    acc.w = fmaf(w, fb.y, acc.w);
                }
            }
        }
        #pragma unroll
        for (int off = 8; off <= 16; off <<= 1) {
            acc.x += __shfl_xor_sync(~0u, acc.x, off);
            acc.y += __shfl_xor_sync(~0u, acc.y, off);
            acc.z += __shfl_xor_sync(~0u, acc.z, off);
            acc.w += __shfl_xor_sync(~0u, acc.w, off);
        }
        int srcl = lane >> 2;
        float c0 = __shfl_sync(~0u, acc.x, srcl);
        float c1 = __shfl_sync(~0u, acc.y, srcl);
        float c2 = __shfl_sync(~0u, acc.z, srcl);
        float c3 = __shfl_sync(~0u, acc.w, srcl);
        int k = lane & 3;
        float sel = (k == 0) ? c0 : (k == 1) ? c1 : (k == 2) ? c2 : c3;
        o = sel * inv_s + bias[lane];
    } else {
        // ---- streaming fallback (unreachable with CAP=128; safety) ----
        float sx = 0.f, sy = 0.f;
        for (int e = rs + 1 + lane; e < re; e += 32) {
            int2 ev = ent2[e];
            float2 a = __half22float2(*reinterpret_cast<__half2*>(&ev.y));
            sx += a.x; sy += a.y;
        }
        #pragma unroll
        for (int off = 16; off; off >>= 1) {
            sx += __shfl_xor_sync(~0u, sx, off);
            sy += __shfl_xor_sync(~0u, sy, off);
        }
        float mex = sx / degc, mey = sy / degc;
        if (MEA == 0 && lane == 0) d_mea[n] = make_float2(mex, mey);
        float m = BIG_NEG, s = 0.f;
        for (int b = rs; b < re; b += 32) {
            int e = b + lane;
            if (e < re) {
                int2 ev = ent2[e];
                float2 eaf = __half22float2(*reinterpret_cast<__half2*>(&ev.y));
                if (e == rs) { eaf.x = mex; eaf.y = mey; }
                float l = __half2float(asrc_in[ev.x]) + adv + eaf.x * ce.x + eaf.y * ce.y;
                l = (l >= 0.f) ? l : 0.2f * l;
                if (l > m) { s = s * __expf(m - l) + 1.f; m = l; }
                else       { s += __expf(l - m); }
            }
        }
        #pragma unroll
        for (int off = 16; off; off >>= 1) {
            float mo = __shfl_xor_sync(~0u, m, off);
            float so = __shfl_xor_sync(~0u, s, off);
            float mn = fmaxf(m, mo);
            s = s * __expf(m - mn) + so * __expf(mo - mn);
            m = mn;
        }
        float inv_s = 1.f / s;
        float acc = 0.f;
        for (int b = rs; b < re; b += 32) {
            int e = b + lane;
            float w = 0.f; int srcn = 0;
            if (e < re) {
                int2 ev = ent2[e];
                float2 eaf = __half22float2(*reinterpret_cast<__half2*>(&ev.y));
                if (e == rs) { eaf.x = mex; eaf.y = mey; }
                float l = __half2float(asrc_in[ev.x]) + adv + eaf.x * ce.x + eaf.y * ce.y;
                l = (l >= 0.f) ? l : 0.2f * l;
                w = __expf(l - m) * inv_s;
                srcn = ev.x;
            }
            int cw = min(32, re - b);
            #pragma unroll 4
            for (int j = 0; j < cw; j++) {
                int   sj = __shfl_sync(~0u, srcn, j);
                float wj = __shfl_sync(~0u, w, j);
                acc = fmaf(wj, __half2float(hlin[sj * H + lane]), acc);
            }
        }
        o = acc + bias[lane];
    }

    if (FUSED) {
        o = fmaxf(o, 0.f);
        float hn = 0.f;
        #pragma unroll
        for (int k2 = 0; k2 < H; k2++)
            hn = fmaf(__shfl_sync(~0u, o, k2), Ws[k2 * H + lane], hn);
        hout16[n * H + lane] = __float2half(hn);
        float ps = hn * As[lane], pd = hn * Ad[lane];
        #pragma unroll
        for (int off = 16; off; off >>= 1) {
            ps += __shfl_xor_sync(~0u, ps, off);
            pd += __shfl_xor_sync(~0u, pd, off);
        }
        if (lane == 0) { asrc_out[n] = __float2half(ps); adst_out[n] = pd; }
    } else {
        houtf[n * H + lane] = o;
    }
}

// ---------------- pool + linear + relu ----------------
__global__ void k_pool(const float* __restrict__ h, const float* __restrict__ lw,
                       const float* __restrict__ lb, float* __restrict__ out) {
    int lane = threadIdx.x & 31;
    int g = blockIdx.x * 8 + (threadIdx.x >> 5);
    if (g >= NG) return;
    const float* p = h + g * NPG * H;
    float acc = 0.f;
    #pragma unroll 6
    for (int r = 0; r < NPG; r++) acc += p[r * H + lane];
    float t = acc * lw[lane];
    #pragma unroll
    for (int off = 16; off; off >>= 1) t += __shfl_xor_sync(~0u, t, off);
    if (lane == 0) out[g] = fmaxf(t + lb[0], 0.f);
}

// ---------------- launch ----------------
extern "C" void kernel_launch(void* const* d_in, const int* in_sizes, int n_in,
                              void* d_out, int out_size) {
    const float*  x    = (const float*)d_in[0];
    const int*    ei   = (const int*)d_in[1];
    const float2* ea   = (const float2*)d_in[2];
    const float*  W0   = (const float*)d_in[3];
    const float*  Ws   = (const float*)d_in[4];
    const float*  as_  = (const float*)d_in[5];
    const float*  ad_  = (const float*)d_in[6];
    const float*  We   = (const float*)d_in[7];
    const float*  ae_  = (const float*)d_in[8];
    const float*  bias = (const float*)d_in[9];
    const float*  lw   = (const float*)d_in[10];
    const float*  lb   = (const float*)d_in[11];
    float* out = (float*)d_out;

    __half *hA, *hB, *asA, *asB; float *hF, *adA, *adB;
    cudaGetSymbolAddress((void**)&hA, d_h16A);
    cudaGetSymbolAddress((void**)&hB, d_h16B);
    cudaGetSymbolAddress((void**)&hF, d_hfin);
    cudaGetSymbolAddress((void**)&asA, d_asA);
    cudaGetSymbolAddress((void**)&asB, d_asB);
    cudaGetSymbolAddress((void**)&adA, d_adA);
    cudaGetSymbolAddress((void**)&adB, d_adB);

    k_initc<<<(NN + 255) / 256, 256>>>(W0, as_, ad_, We, ae_);
    k_scatl0<<<SCB + NN / 8, 256>>>(ei, ea, x, W0);

    k_agg<1, 0><<<NN / 8, 256>>>(hB, bias + 0 * H, 0, Ws + 0 * H * H, as_ + 1 * H, ad_ + 1 * H,
                                 asA, adA, hA, nullptr, asB, adB);
    k_agg<1, 1><<<NN / 8, 256>>>(hA, bias + 1 * H, 1, Ws + 1 * H * H, as_ + 2 * H, ad_ + 2 * H,
                                 asB, adB, hB, nullptr, asA, adA);
    k_agg<1, 1><<<NN / 8, 256>>>(hB, bias + 2 * H, 2, Ws + 2 * H * H, as_ + 3 * H, ad_ + 3 * H,
                                 asA, adA, hA, nullptr, asB, adB);
    k_agg<0, 1><<<NN / 8, 256>>>(hA, bias + 3 * H, 3, nullptr, nullptr, nullptr,
                                 asB, adB, nullptr, hF, nullptr, nullptr);
    k_pool<<<128, 256>>>(hF, lw, lb, out);
}